// round 1
// baseline (speedup 1.0000x reference)
#include <cuda_runtime.h>
#include <cuda_fp16.h>
#include <cstdint>

#define SEQ 4096
#define DIM 768
#define NHEAD 12
#define DHEAD 64
#define POST_SCALE 19.595917942265423f  // sqrt(384)

// ---- device scratch (allocation-free rule: static __device__ arrays) ----
__device__ float g_Q[SEQ * DIM];
__device__ float g_K[SEQ * DIM];
__device__ float g_V[SEQ * DIM];
__device__ float g_attn[SEQ * DIM];
__device__ __half g_P[(size_t)NHEAD * SEQ * SEQ];  // 402 MB

__device__ __forceinline__ uint32_t f2tf(float f) {
    uint32_t u;
    asm("cvt.rna.tf32.f32 %0, %1;" : "=r"(u) : "f"(f));
    return u;
}

__device__ __forceinline__ void mma8(float* c, const uint32_t* a, const uint32_t* b) {
    asm volatile(
        "mma.sync.aligned.m16n8k8.row.col.f32.tf32.tf32.f32 "
        "{%0,%1,%2,%3}, {%4,%5,%6,%7}, {%8,%9}, {%0,%1,%2,%3};\n"
        : "+f"(c[0]), "+f"(c[1]), "+f"(c[2]), "+f"(c[3])
        : "r"(a[0]), "r"(a[1]), "r"(a[2]), "r"(a[3]), "r"(b[0]), "r"(b[1]));
}

// ============================================================
// Kernel 1/4: Y[4096,768] = X[4096,768] @ W[768,768]^T + bias
// Tile: BM=128, BN=64, BK=32. 8 warps (4M x 2N), warp 32x32.
// ============================================================
__global__ __launch_bounds__(256) void linear_kernel(
    const float* __restrict__ X, const float* __restrict__ W,
    const float* __restrict__ bias, float* __restrict__ Y)
{
    __shared__ uint32_t As[128][36];  // stride 36 == 4 mod 32: conflict-free frag reads
    __shared__ uint32_t Bs[32][65];   // stride 65 odd: conflict-free stores

    const int tid = threadIdx.x;
    const int lane = tid & 31, warp = tid >> 5;
    const int wm = warp >> 1, wn = warp & 1;
    const int m0 = blockIdx.y * 128, n0 = blockIdx.x * 64;
    const int g = lane >> 2, t4 = lane & 3;

    float c[2][4][4];
#pragma unroll
    for (int mt = 0; mt < 2; mt++)
#pragma unroll
        for (int nt = 0; nt < 4; nt++)
#pragma unroll
            for (int r = 0; r < 4; r++) c[mt][nt][r] = 0.f;

    for (int kt = 0; kt < DIM; kt += 32) {
#pragma unroll
        for (int i = 0; i < 16; i++) {
            int idx = tid + i * 256;
            int r = idx >> 5, cc = idx & 31;
            As[r][cc] = f2tf(X[(size_t)(m0 + r) * DIM + kt + cc]);
        }
#pragma unroll
        for (int i = 0; i < 8; i++) {
            int idx = tid + i * 256;
            int n = idx >> 5, k = idx & 31;
            Bs[k][n] = f2tf(W[(size_t)(n0 + n) * DIM + kt + k]);
        }
        __syncthreads();
#pragma unroll
        for (int ks = 0; ks < 4; ks++) {
            const int kk = ks * 8;
            uint32_t a[2][4], b[4][2];
#pragma unroll
            for (int mt = 0; mt < 2; mt++) {
                int r0 = wm * 32 + mt * 16;
                a[mt][0] = As[r0 + g][kk + t4];
                a[mt][1] = As[r0 + g + 8][kk + t4];
                a[mt][2] = As[r0 + g][kk + t4 + 4];
                a[mt][3] = As[r0 + g + 8][kk + t4 + 4];
            }
#pragma unroll
            for (int nt = 0; nt < 4; nt++) {
                int nb = wn * 32 + nt * 8;
                b[nt][0] = Bs[kk + t4][nb + g];
                b[nt][1] = Bs[kk + t4 + 4][nb + g];
            }
#pragma unroll
            for (int mt = 0; mt < 2; mt++)
#pragma unroll
                for (int nt = 0; nt < 4; nt++) mma8(c[mt][nt], a[mt], b[nt]);
        }
        __syncthreads();
    }
#pragma unroll
    for (int mt = 0; mt < 2; mt++)
#pragma unroll
        for (int nt = 0; nt < 4; nt++)
#pragma unroll
            for (int r = 0; r < 4; r++) {
                int row = m0 + wm * 32 + mt * 16 + g + (r >> 1) * 8;
                int col = n0 + wn * 32 + nt * 8 + t4 * 2 + (r & 1);
                Y[(size_t)row * DIM + col] = c[mt][nt][r] + bias[col];
            }
}

// ============================================================
// Kernel 2: scores for all 12 heads on a 64x64 (s,t) tile,
// softmax over the HEAD axis, write P (fp16, *sqrt(384)).
// scores[h,s,t] = sum_d K[s, h*64+d] * Q[t, h*64+d]
// Smem: fp32 sc[12][64][64] (swizzled) + A/B operand tiles.
// ============================================================
#define SC_BYTES (12 * 64 * 64 * 4)            // 196608
#define AS2_OFF  SC_BYTES
#define AS2_BYTES (64 * 68 * 4)                // 17408
#define BS2_OFF  (AS2_OFF + AS2_BYTES)
#define BS2_BYTES (64 * 65 * 4)                // 16640
#define SM2_TOTAL (BS2_OFF + BS2_BYTES)        // 230656

__global__ __launch_bounds__(256) void scores_softmax_kernel(
    const float* __restrict__ Qm, const float* __restrict__ Km,
    __half* __restrict__ P)
{
    extern __shared__ unsigned char smraw[];
    float* sc = (float*)smraw;
    uint32_t* As = (uint32_t*)(smraw + AS2_OFF);  // [64][68]
    uint32_t* Bs = (uint32_t*)(smraw + BS2_OFF);  // [64][65]

    const int tid = threadIdx.x;
    const int lane = tid & 31, warp = tid >> 5;
    const int wm = warp >> 1, wn = warp & 1;  // 4M x 2N, warp tile 16x32
    const int s0 = blockIdx.y * 64, t0 = blockIdx.x * 64;
    const int g = lane >> 2, t4 = lane & 3;

    for (int h = 0; h < NHEAD; h++) {
        const int hc = h * DHEAD;
#pragma unroll
        for (int i = 0; i < 16; i++) {
            int idx = tid + i * 256;
            int r = idx >> 6, cc = idx & 63;
            As[r * 68 + cc] = f2tf(Km[(size_t)(s0 + r) * DIM + hc + cc]);
        }
#pragma unroll
        for (int i = 0; i < 16; i++) {
            int idx = tid + i * 256;
            int n = idx >> 6, k = idx & 63;
            Bs[k * 65 + n] = f2tf(Qm[(size_t)(t0 + n) * DIM + hc + k]);
        }
        __syncthreads();

        float cr[4][4];
#pragma unroll
        for (int nt = 0; nt < 4; nt++)
#pragma unroll
            for (int r = 0; r < 4; r++) cr[nt][r] = 0.f;

#pragma unroll
        for (int ks = 0; ks < 8; ks++) {
            const int kk = ks * 8;
            uint32_t a[4];
            const int r0 = wm * 16;
            a[0] = As[(r0 + g) * 68 + kk + t4];
            a[1] = As[(r0 + g + 8) * 68 + kk + t4];
            a[2] = As[(r0 + g) * 68 + kk + t4 + 4];
            a[3] = As[(r0 + g + 8) * 68 + kk + t4 + 4];
#pragma unroll
            for (int nt = 0; nt < 4; nt++) {
                uint32_t b[2];
                const int nb = wn * 32 + nt * 8;
                b[0] = Bs[(kk + t4) * 65 + nb + g];
                b[1] = Bs[(kk + t4 + 4) * 65 + nb + g];
                mma8(cr[nt], a, b);
            }
        }
        // swizzled store: bank = f(col ^ ((row&7)<<3)) -> <=2-way conflicts
#pragma unroll
        for (int nt = 0; nt < 4; nt++)
#pragma unroll
            for (int r = 0; r < 4; r++) {
                int row = wm * 16 + g + (r >> 1) * 8;
                int col = wn * 32 + nt * 8 + t4 * 2 + (r & 1);
                sc[h * 4096 + row * 64 + (col ^ ((row & 7) << 3))] = cr[nt][r];
            }
        __syncthreads();
    }

    // softmax over h per (s,t) cell; write P = exp/sum * sqrt(384)
#pragma unroll
    for (int i = 0; i < 16; i++) {
        int cell = tid + i * 256;
        int s = cell >> 6, t = cell & 63;
        int tsw = t ^ ((s & 7) << 3);
        float v[NHEAD];
        float m = -1e30f;
#pragma unroll
        for (int h = 0; h < NHEAD; h++) {
            v[h] = sc[h * 4096 + s * 64 + tsw];
            m = fmaxf(m, v[h]);
        }
        float z = 0.f;
#pragma unroll
        for (int h = 0; h < NHEAD; h++) {
            v[h] = __expf(v[h] - m);
            z += v[h];
        }
        float inv = POST_SCALE / z;
#pragma unroll
        for (int h = 0; h < NHEAD; h++)
            P[((size_t)h * SEQ + s0 + s) * SEQ + (t0 + t)] = __float2half(v[h] * inv);
    }
}

// ============================================================
// Kernel 3: out_attn[s, h*64+d] = sum_t P[h,s,t] * V[t, h*64+d]
// Per-head GEMM: [4096 x 4096] @ [4096 x 64]. BM=128,BN=64,BK=32
// ============================================================
__global__ __launch_bounds__(256) void pv_kernel(
    const __half* __restrict__ P, const float* __restrict__ Vm,
    float* __restrict__ Y)
{
    __shared__ uint32_t As[128][36];
    __shared__ uint32_t Bs[32][72];  // stride 72 == 8 mod 32: conflict-free frag reads

    const int tid = threadIdx.x;
    const int lane = tid & 31, warp = tid >> 5;
    const int wm = warp >> 1, wn = warp & 1;
    const int h = blockIdx.z;
    const int m0 = blockIdx.y * 128;
    const int g = lane >> 2, t4 = lane & 3;

    float c[2][4][4];
#pragma unroll
    for (int mt = 0; mt < 2; mt++)
#pragma unroll
        for (int nt = 0; nt < 4; nt++)
#pragma unroll
            for (int r = 0; r < 4; r++) c[mt][nt][r] = 0.f;

    for (int kt = 0; kt < SEQ; kt += 32) {
#pragma unroll
        for (int i = 0; i < 16; i++) {
            int idx = tid + i * 256;
            int r = idx >> 5, cc = idx & 31;
            As[r][cc] = f2tf(__half2float(
                P[((size_t)h * SEQ + m0 + r) * SEQ + kt + cc]));
        }
#pragma unroll
        for (int i = 0; i < 8; i++) {
            int idx = tid + i * 256;
            int n = idx & 63, k = idx >> 6;
            Bs[k][n] = f2tf(Vm[(size_t)(kt + k) * DIM + h * DHEAD + n]);
        }
        __syncthreads();
#pragma unroll
        for (int ks = 0; ks < 4; ks++) {
            const int kk = ks * 8;
            uint32_t a[2][4], b[4][2];
#pragma unroll
            for (int mt = 0; mt < 2; mt++) {
                int r0 = wm * 32 + mt * 16;
                a[mt][0] = As[r0 + g][kk + t4];
                a[mt][1] = As[r0 + g + 8][kk + t4];
                a[mt][2] = As[r0 + g][kk + t4 + 4];
                a[mt][3] = As[r0 + g + 8][kk + t4 + 4];
            }
#pragma unroll
            for (int nt = 0; nt < 4; nt++) {
                int nb = wn * 32 + nt * 8;
                b[nt][0] = Bs[kk + t4][nb + g];
                b[nt][1] = Bs[kk + t4 + 4][nb + g];
            }
#pragma unroll
            for (int mt = 0; mt < 2; mt++)
#pragma unroll
                for (int nt = 0; nt < 4; nt++) mma8(c[mt][nt], a[mt], b[nt]);
        }
        __syncthreads();
    }
#pragma unroll
    for (int mt = 0; mt < 2; mt++)
#pragma unroll
        for (int nt = 0; nt < 4; nt++)
#pragma unroll
            for (int r = 0; r < 4; r++) {
                int row = m0 + wm * 32 + mt * 16 + g + (r >> 1) * 8;
                int col = wn * 32 + nt * 8 + t4 * 2 + (r & 1);
                Y[(size_t)row * DIM + h * DHEAD + col] = c[mt][nt][r];
            }
}

// ============================================================
extern "C" void kernel_launch(void* const* d_in, const int* in_sizes, int n_in,
                              void* d_out, int out_size)
{
    const float* x  = (const float*)d_in[0];
    const float* Wq = (const float*)d_in[1];
    const float* bq = (const float*)d_in[2];
    const float* Wk = (const float*)d_in[3];
    const float* bk = (const float*)d_in[4];
    const float* Wv = (const float*)d_in[5];
    const float* bv = (const float*)d_in[6];
    const float* Wo = (const float*)d_in[7];
    const float* bo = (const float*)d_in[8];
    float* out = (float*)d_out;

    float *Q, *K, *V, *A;
    __half* P;
    cudaGetSymbolAddress((void**)&Q, g_Q);
    cudaGetSymbolAddress((void**)&K, g_K);
    cudaGetSymbolAddress((void**)&V, g_V);
    cudaGetSymbolAddress((void**)&A, g_attn);
    cudaGetSymbolAddress((void**)&P, g_P);

    cudaFuncSetAttribute(scores_softmax_kernel,
                         cudaFuncAttributeMaxDynamicSharedMemorySize, SM2_TOTAL);

    dim3 glin(DIM / 64, SEQ / 128);
    linear_kernel<<<glin, 256>>>(x, Wq, bq, Q);
    linear_kernel<<<glin, 256>>>(x, Wk, bk, K);
    linear_kernel<<<glin, 256>>>(x, Wv, bv, V);

    dim3 gsc(SEQ / 64, SEQ / 64);
    scores_softmax_kernel<<<gsc, 256, SM2_TOTAL>>>(Q, K, P);

    dim3 gpv(1, SEQ / 128, NHEAD);
    pv_kernel<<<gpv, 256>>>(P, V, A);

    linear_kernel<<<glin, 256>>>(A, Wo, bo, out);
}

// round 2
// speedup vs baseline: 3.1839x; 3.1839x over previous
#include <cuda_runtime.h>
#include <cuda_fp16.h>
#include <cstdint>

#define SEQ 4096
#define DIM 768
#define NHEAD 12
#define DHEAD 64
#define POST_SCALE 19.595917942265423f  // sqrt(384)

// ---- device scratch (allocation-free rule) ----
__device__ __half g_x16[SEQ * DIM];
__device__ __half g_wq[DIM * DIM];
__device__ __half g_wk[DIM * DIM];
__device__ __half g_wv[DIM * DIM];
__device__ __half g_wo[DIM * DIM];
__device__ __half g_Qh[SEQ * DIM];
__device__ __half g_Kh[SEQ * DIM];
__device__ __half g_Vh[SEQ * DIM];
__device__ __half g_Ah[SEQ * DIM];
__device__ __half g_P[(size_t)NHEAD * SEQ * SEQ];  // 402 MB

// ---------------- PTX helpers ----------------
__device__ __forceinline__ void cp16(uint32_t dst, const void* src) {
    asm volatile("cp.async.cg.shared.global [%0], [%1], 16;\n" :: "r"(dst), "l"(src));
}
#define CP_COMMIT() asm volatile("cp.async.commit_group;\n")
#define CP_WAIT0()  asm volatile("cp.async.wait_group 0;\n")
#define CP_WAIT1()  asm volatile("cp.async.wait_group 1;\n")

#define LDSM4(R, a) asm volatile( \
    "ldmatrix.sync.aligned.m8n8.x4.shared.b16 {%0,%1,%2,%3}, [%4];" \
    : "=r"((R)[0]), "=r"((R)[1]), "=r"((R)[2]), "=r"((R)[3]) : "r"(a))
#define LDSM4T(R, a) asm volatile( \
    "ldmatrix.sync.aligned.m8n8.x4.trans.shared.b16 {%0,%1,%2,%3}, [%4];" \
    : "=r"((R)[0]), "=r"((R)[1]), "=r"((R)[2]), "=r"((R)[3]) : "r"(a))
#define LDSM2(R, a) asm volatile( \
    "ldmatrix.sync.aligned.m8n8.x2.shared.b16 {%0,%1}, [%2];" \
    : "=r"((R)[0]), "=r"((R)[1]) : "r"(a))

__device__ __forceinline__ void mma16(float* c, const uint32_t* a, const uint32_t* b) {
    asm volatile(
        "mma.sync.aligned.m16n8k16.row.col.f32.f16.f16.f32 "
        "{%0,%1,%2,%3},{%4,%5,%6,%7},{%8,%9},{%0,%1,%2,%3};\n"
        : "+f"(c[0]), "+f"(c[1]), "+f"(c[2]), "+f"(c[3])
        : "r"(a[0]), "r"(a[1]), "r"(a[2]), "r"(a[3]), "r"(b[0]), "r"(b[1]));
}

// swizzled byte offset within a tile of 128B rows (8x16B chunks, chunk ^= row&7)
__device__ __forceinline__ uint32_t swz(int row, int ch) {
    return (uint32_t)(row * 128 + ((ch ^ (row & 7)) << 4));
}

// ---------------- fp32 -> fp16 convert ----------------
__global__ void cvt_kernel(const float* __restrict__ src, __half* __restrict__ dst, int n2) {
    int i = blockIdx.x * blockDim.x + threadIdx.x;
    int stride = gridDim.x * blockDim.x;
    const float2* s2 = (const float2*)src;
    __half2* d2 = (__half2*)dst;
    for (; i < n2; i += stride) {
        float2 v = s2[i];
        d2[i] = __floats2half2_rn(v.x, v.y);
    }
}

// ============================================================
// Linear: Y[4096,768] = X16 @ W16^T + b.  BM=128 BN=64 BK=64.
// 256 threads, 8 warps (4m x 2n), warp tile 32x32.
// ============================================================
template<bool F16OUT>
__global__ __launch_bounds__(256) void linear16(
    const __half* __restrict__ X, const __half* __restrict__ W,
    const float* __restrict__ bias, void* __restrict__ Yv)
{
    __shared__ __align__(16) unsigned char smbuf[49152];  // 2 x (16K A + 8K B)
    const uint32_t smb = (uint32_t)__cvta_generic_to_shared(smbuf);
    const int tid = threadIdx.x, lane = tid & 31, warp = tid >> 5;
    const int wm = warp >> 1, wn = warp & 1;
    const int m0 = blockIdx.y * 128, n0 = blockIdx.x * 64;
    const int g = lane >> 2, t4 = lane & 3;

    float c[2][4][4];
#pragma unroll
    for (int mt = 0; mt < 2; mt++)
#pragma unroll
        for (int nt = 0; nt < 4; nt++)
#pragma unroll
            for (int r = 0; r < 4; r++) c[mt][nt][r] = 0.f;

    // prologue load kt=0 into buf0
    {
        uint32_t ab = smb, bb = smb + 16384;
#pragma unroll
        for (int i = 0; i < 4; i++) {
            int op = tid + i * 256; int row = op >> 3, ch = op & 7;
            cp16(ab + swz(row, ch), X + (size_t)(m0 + row) * DIM + ch * 8);
        }
#pragma unroll
        for (int i = 0; i < 2; i++) {
            int op = tid + i * 256; int row = op >> 3, ch = op & 7;
            cp16(bb + swz(row, ch), W + (size_t)(n0 + row) * DIM + ch * 8);
        }
        CP_COMMIT();
    }

    for (int it = 0; it < 12; it++) {
        if (it < 11) {
            int kt = (it + 1) * 64;
            uint32_t ab = smb + ((it + 1) & 1) * 24576, bb = ab + 16384;
#pragma unroll
            for (int i = 0; i < 4; i++) {
                int op = tid + i * 256; int row = op >> 3, ch = op & 7;
                cp16(ab + swz(row, ch), X + (size_t)(m0 + row) * DIM + kt + ch * 8);
            }
#pragma unroll
            for (int i = 0; i < 2; i++) {
                int op = tid + i * 256; int row = op >> 3, ch = op & 7;
                cp16(bb + swz(row, ch), W + (size_t)(n0 + row) * DIM + kt + ch * 8);
            }
            CP_COMMIT();
            CP_WAIT1();
        } else {
            CP_WAIT0();
        }
        __syncthreads();

        uint32_t ab = smb + (it & 1) * 24576, bb = ab + 16384;
#pragma unroll
        for (int ks = 0; ks < 4; ks++) {
            uint32_t a[2][4], b[2][4];
#pragma unroll
            for (int mt = 0; mt < 2; mt++) {
                int row = wm * 32 + mt * 16 + (lane & 15);
                int ch = ks * 2 + (lane >> 4);
                LDSM4(a[mt], ab + swz(row, ch));
            }
#pragma unroll
            for (int p = 0; p < 2; p++) {
                int row = wn * 32 + p * 16 + (lane & 7) + ((lane >> 4) << 3);
                int ch = ks * 2 + ((lane >> 3) & 1);
                LDSM4(b[p], bb + swz(row, ch));
            }
#pragma unroll
            for (int mt = 0; mt < 2; mt++) {
                mma16(c[mt][0], a[mt], &b[0][0]);
                mma16(c[mt][1], a[mt], &b[0][2]);
                mma16(c[mt][2], a[mt], &b[1][0]);
                mma16(c[mt][3], a[mt], &b[1][2]);
            }
        }
        __syncthreads();
    }

#pragma unroll
    for (int mt = 0; mt < 2; mt++)
#pragma unroll
        for (int nt = 0; nt < 4; nt++) {
            int col = n0 + wn * 32 + nt * 8 + t4 * 2;
            float b0 = bias[col], b1 = bias[col + 1];
#pragma unroll
            for (int rh = 0; rh < 2; rh++) {
                int row = m0 + wm * 32 + mt * 16 + g + rh * 8;
                float v0 = c[mt][nt][rh * 2] + b0;
                float v1 = c[mt][nt][rh * 2 + 1] + b1;
                if (F16OUT) {
                    *(__half2*)((__half*)Yv + (size_t)row * DIM + col) =
                        __floats2half2_rn(v0, v1);
                } else {
                    float2 v = {v0, v1};
                    *(float2*)((float*)Yv + (size_t)row * DIM + col) = v;
                }
            }
        }
}

// ============================================================
// Scores + head-softmax, fused, softmax in registers.
// CTA: 64 (s) x 32 (t). 512 threads = 16 warps (4s x 4t),
// warp tile m16 x n8, all 12 heads accumulated in registers.
// P[h,s,t] = exp(score)/sum_h exp * sqrt(384), fp16.
// ============================================================
#define SC_SMEM 61440  // max(2*12288 staging, 12*64*40*2 P-stage)

__global__ __launch_bounds__(512) void scores16(
    const __half* __restrict__ Qh, const __half* __restrict__ Kh,
    __half* __restrict__ P)
{
    extern __shared__ __align__(16) unsigned char sm[];
    const uint32_t smb = (uint32_t)__cvta_generic_to_shared(sm);
    const int tid = threadIdx.x, lane = tid & 31, warp = tid >> 5;
    const int wm = warp >> 2, wn = warp & 3;
    const int s0 = blockIdx.y * 64, t0 = blockIdx.x * 32;
    const int g = lane >> 2, t4 = lane & 3;

    float acc[NHEAD][4];
#pragma unroll
    for (int h = 0; h < NHEAD; h++)
#pragma unroll
        for (int r = 0; r < 4; r++) acc[h][r] = 0.f;

    // staging buf b at smb + b*12288: K 64 rows (8KB) then Q 32 rows (4KB)
    // prologue: head 0 into buf 0
    {
        int op = tid;  // K part: ops 0..511
        int row = op >> 3, ch = op & 7;
        cp16(smb + swz(row, ch), Kh + (size_t)(s0 + row) * DIM + ch * 8);
        if (tid < 256) {
            int q = tid; int qrow = q >> 3, qch = q & 7;
            cp16(smb + 8192 + swz(qrow, qch), Qh + (size_t)(t0 + qrow) * DIM + qch * 8);
        }
        CP_COMMIT();
    }

#pragma unroll
    for (int h = 0; h < NHEAD; h++) {
        if (h < NHEAD - 1) {
            uint32_t base = smb + ((h + 1) & 1) * 12288;
            int hc = (h + 1) * DHEAD;
            int row = tid >> 3, ch = tid & 7;
            cp16(base + swz(row, ch), Kh + (size_t)(s0 + row) * DIM + hc + ch * 8);
            if (tid < 256) {
                int qrow = tid >> 3, qch = tid & 7;
                cp16(base + 8192 + swz(qrow, qch),
                     Qh + (size_t)(t0 + qrow) * DIM + hc + qch * 8);
            }
            CP_COMMIT();
            CP_WAIT1();
        } else {
            CP_WAIT0();
        }
        __syncthreads();

        uint32_t kb = smb + (h & 1) * 12288, qb = kb + 8192;
#pragma unroll
        for (int ks = 0; ks < 4; ks++) {
            uint32_t a[4], b[2];
            {
                int row = wm * 16 + (lane & 15);
                int ch = ks * 2 + (lane >> 4);
                LDSM4(a, kb + swz(row, ch));
            }
            {
                int row = wn * 8 + (lane & 7);
                int ch = ks * 2 + ((lane >> 3) & 1);
                LDSM2(b, qb + swz(row, ch));
            }
            mma16(acc[h], a, b);
        }
        __syncthreads();
    }

    // softmax over heads, fully in registers (scores bounded, no max needed)
    float inv[4];
#pragma unroll
    for (int j = 0; j < 4; j++) {
        float s = 0.f;
#pragma unroll
        for (int h = 0; h < NHEAD; h++) {
            float e = __expf(acc[h][j]);
            acc[h][j] = e;
            s += e;
        }
        inv[j] = POST_SCALE / s;
    }

    // stage P tile to smem (rows padded to 40 halves = 80B), then coalesced out
    __half* sp = (__half*)sm;
#pragma unroll
    for (int h = 0; h < NHEAD; h++)
#pragma unroll
        for (int j = 0; j < 4; j++) {
            int sl = wm * 16 + g + (j >> 1) * 8;
            int tl = wn * 8 + t4 * 2 + (j & 1);
            sp[(h * 64 + sl) * 40 + tl] = __float2half_rn(acc[h][j] * inv[j]);
        }
    __syncthreads();

#pragma unroll
    for (int i = 0; i < 6; i++) {
        int op = tid + i * 512;       // 3072 ops: 768 rows x 4 x 16B
        int row = op >> 2, cht = op & 3;
        int h = row >> 6, s = row & 63;
        uint4 v = *(const uint4*)(sp + row * 40 + cht * 8);
        *(uint4*)(P + ((size_t)h * SEQ + s0 + s) * SEQ + t0 + cht * 8) = v;
    }
}

// ============================================================
// PV: out[s, h*64+d] = sum_t P[h,s,t] * V[t, h*64+d], fp16 out.
// BM=64, BN=64, BK=64. 256 threads, 8 warps (4m x 2n), warp 16x32.
// ============================================================
__global__ __launch_bounds__(256) void pv16(
    const __half* __restrict__ P, const __half* __restrict__ V,
    __half* __restrict__ Y)
{
    __shared__ __align__(16) unsigned char smbuf[32768];  // 2 x (8K A + 8K B)
    const uint32_t smb = (uint32_t)__cvta_generic_to_shared(smbuf);
    const int tid = threadIdx.x, lane = tid & 31, warp = tid >> 5;
    const int wm = warp >> 1, wn = warp & 1;
    const int h = blockIdx.z;
    const int m0 = blockIdx.y * 64;
    const int g = lane >> 2, t4 = lane & 3;
    const __half* Ph = P + (size_t)h * SEQ * SEQ;

    float c[4][4];
#pragma unroll
    for (int nt = 0; nt < 4; nt++)
#pragma unroll
        for (int r = 0; r < 4; r++) c[nt][r] = 0.f;

    // prologue kt=0
    {
        uint32_t ab = smb, bb = smb + 8192;
        {
            int op = tid; int row = op >> 3, ch = op & 7;        // A: 512 ops x1? no: 512 ops total, 256 thr -> 2
            cp16(ab + swz(row, ch), Ph + (size_t)(m0 + row) * SEQ + ch * 8);
            op = tid + 256; row = op >> 3; ch = op & 7;
            cp16(ab + swz(row, ch), Ph + (size_t)(m0 + row) * SEQ + ch * 8);
        }
        {
            int op = tid; int row = op >> 3, ch = op & 7;
            cp16(bb + swz(row, ch), V + (size_t)row * DIM + h * DHEAD + ch * 8);
            op = tid + 256; row = op >> 3; ch = op & 7;
            cp16(bb + swz(row, ch), V + (size_t)row * DIM + h * DHEAD + ch * 8);
        }
        CP_COMMIT();
    }

    for (int it = 0; it < 64; it++) {
        if (it < 63) {
            int kt = (it + 1) * 64;
            uint32_t ab = smb + ((it + 1) & 1) * 16384, bb = ab + 8192;
#pragma unroll
            for (int i = 0; i < 2; i++) {
                int op = tid + i * 256; int row = op >> 3, ch = op & 7;
                cp16(ab + swz(row, ch), Ph + (size_t)(m0 + row) * SEQ + kt + ch * 8);
            }
#pragma unroll
            for (int i = 0; i < 2; i++) {
                int op = tid + i * 256; int row = op >> 3, ch = op & 7;
                cp16(bb + swz(row, ch), V + (size_t)(kt + row) * DIM + h * DHEAD + ch * 8);
            }
            CP_COMMIT();
            CP_WAIT1();
        } else {
            CP_WAIT0();
        }
        __syncthreads();

        uint32_t ab = smb + (it & 1) * 16384, bb = ab + 8192;
#pragma unroll
        for (int ks = 0; ks < 4; ks++) {
            uint32_t a[4], b[2][4];
            {
                int row = wm * 16 + (lane & 15);
                int ch = ks * 2 + (lane >> 4);
                LDSM4(a, ab + swz(row, ch));
            }
#pragma unroll
            for (int p = 0; p < 2; p++) {
                int row = ks * 16 + (lane & 15);
                int ch = wn * 4 + p * 2 + (lane >> 4);
                LDSM4T(b[p], bb + swz(row, ch));
            }
            mma16(c[0], a, &b[0][0]);
            mma16(c[1], a, &b[0][2]);
            mma16(c[2], a, &b[1][0]);
            mma16(c[3], a, &b[1][2]);
        }
        __syncthreads();
    }

#pragma unroll
    for (int nt = 0; nt < 4; nt++) {
        int col = h * DHEAD + wn * 32 + nt * 8 + t4 * 2;
#pragma unroll
        for (int rh = 0; rh < 2; rh++) {
            int row = m0 + wm * 16 + g + rh * 8;
            *(__half2*)(Y + (size_t)row * DIM + col) =
                __floats2half2_rn(c[nt][rh * 2], c[nt][rh * 2 + 1]);
        }
    }
}

// ============================================================
extern "C" void kernel_launch(void* const* d_in, const int* in_sizes, int n_in,
                              void* d_out, int out_size)
{
    const float* x  = (const float*)d_in[0];
    const float* Wq = (const float*)d_in[1];
    const float* bq = (const float*)d_in[2];
    const float* Wk = (const float*)d_in[3];
    const float* bk = (const float*)d_in[4];
    const float* Wv = (const float*)d_in[5];
    const float* bv = (const float*)d_in[6];
    const float* Wo = (const float*)d_in[7];
    const float* bo = (const float*)d_in[8];
    float* out = (float*)d_out;

    __half *x16, *wq, *wk, *wv, *wo, *Qh, *Kh, *Vh, *Ah, *P;
    cudaGetSymbolAddress((void**)&x16, g_x16);
    cudaGetSymbolAddress((void**)&wq, g_wq);
    cudaGetSymbolAddress((void**)&wk, g_wk);
    cudaGetSymbolAddress((void**)&wv, g_wv);
    cudaGetSymbolAddress((void**)&wo, g_wo);
    cudaGetSymbolAddress((void**)&Qh, g_Qh);
    cudaGetSymbolAddress((void**)&Kh, g_Kh);
    cudaGetSymbolAddress((void**)&Vh, g_Vh);
    cudaGetSymbolAddress((void**)&Ah, g_Ah);
    cudaGetSymbolAddress((void**)&P, g_P);

    cudaFuncSetAttribute(scores16, cudaFuncAttributeMaxDynamicSharedMemorySize, SC_SMEM);

    cvt_kernel<<<1024, 256>>>(x,  x16, SEQ * DIM / 2);
    cvt_kernel<<<512,  256>>>(Wq, wq,  DIM * DIM / 2);
    cvt_kernel<<<512,  256>>>(Wk, wk,  DIM * DIM / 2);
    cvt_kernel<<<512,  256>>>(Wv, wv,  DIM * DIM / 2);
    cvt_kernel<<<512,  256>>>(Wo, wo,  DIM * DIM / 2);

    dim3 glin(DIM / 64, SEQ / 128);
    linear16<true><<<glin, 256>>>(x16, wq, bq, Qh);
    linear16<true><<<glin, 256>>>(x16, wk, bk, Kh);
    linear16<true><<<glin, 256>>>(x16, wv, bv, Vh);

    dim3 gsc(SEQ / 32, SEQ / 64);
    scores16<<<gsc, 512, SC_SMEM>>>(Qh, Kh, P);

    dim3 gpv(1, SEQ / 64, NHEAD);
    pv16<<<gpv, 256>>>(P, Vh, Ah);

    linear16<false><<<glin, 256>>>(Ah, wo, bo, out);
}

// round 3
// speedup vs baseline: 4.1812x; 1.3132x over previous
#include <cuda_runtime.h>
#include <cuda_fp16.h>
#include <cstdint>

#define SEQ 4096
#define DIM 768
#define NHEAD 12
#define DHEAD 64
#define POST_SCALE 19.595917942265423f  // sqrt(384)

// ---- device scratch (allocation-free rule) ----
__device__ __half g_x16[SEQ * DIM];
__device__ __half g_w[4 * DIM * DIM];          // packed Wq,Wk,Wv,Wo (fp16)
__device__ float  g_bqkv[3 * DIM];             // packed bq,bk,bv
__device__ __half g_QKV[3 * SEQ * DIM];        // Q,K,V planes (fp16)
__device__ __half g_Ah[SEQ * DIM];
__device__ __half g_P[(size_t)NHEAD * SEQ * SEQ];  // 402 MB

// ---------------- PTX helpers ----------------
__device__ __forceinline__ void cp16(uint32_t dst, const void* src) {
    asm volatile("cp.async.cg.shared.global [%0], [%1], 16;\n" :: "r"(dst), "l"(src));
}
#define CP_COMMIT() asm volatile("cp.async.commit_group;\n")
#define CP_WAIT0()  asm volatile("cp.async.wait_group 0;\n")
#define CP_WAIT1()  asm volatile("cp.async.wait_group 1;\n")

#define LDSM4(R, a) asm volatile( \
    "ldmatrix.sync.aligned.m8n8.x4.shared.b16 {%0,%1,%2,%3}, [%4];" \
    : "=r"((R)[0]), "=r"((R)[1]), "=r"((R)[2]), "=r"((R)[3]) : "r"(a))
#define LDSM4T(R, a) asm volatile( \
    "ldmatrix.sync.aligned.m8n8.x4.trans.shared.b16 {%0,%1,%2,%3}, [%4];" \
    : "=r"((R)[0]), "=r"((R)[1]), "=r"((R)[2]), "=r"((R)[3]) : "r"(a))

__device__ __forceinline__ void mma16(float* c, const uint32_t* a, const uint32_t* b) {
    asm volatile(
        "mma.sync.aligned.m16n8k16.row.col.f32.f16.f16.f32 "
        "{%0,%1,%2,%3},{%4,%5,%6,%7},{%8,%9},{%0,%1,%2,%3};\n"
        : "+f"(c[0]), "+f"(c[1]), "+f"(c[2]), "+f"(c[3])
        : "r"(a[0]), "r"(a[1]), "r"(a[2]), "r"(a[3]), "r"(b[0]), "r"(b[1]));
}

// swizzled byte offset within a tile of 128B rows (8x16B chunks, chunk ^= row&7)
__device__ __forceinline__ uint32_t swz(int row, int ch) {
    return (uint32_t)(row * 128 + ((ch ^ (row & 7)) << 4));
}

// ---------------- merged fp32->fp16 convert + packing ----------------
#define NX2 (SEQ * DIM / 2)
#define NW2 (DIM * DIM / 2)
__global__ void cvt_all(
    const float* __restrict__ x,
    const float* __restrict__ Wq, const float* __restrict__ Wk,
    const float* __restrict__ Wv, const float* __restrict__ Wo,
    const float* __restrict__ bq, const float* __restrict__ bk,
    const float* __restrict__ bv,
    __half* __restrict__ x16, __half* __restrict__ wpk,
    float* __restrict__ bqkv)
{
    int i = blockIdx.x * blockDim.x + threadIdx.x;
    int stride = gridDim.x * blockDim.x;
    if (i < 3 * DIM) {
        bqkv[i] = (i < DIM) ? bq[i] : (i < 2 * DIM ? bk[i - DIM] : bv[i - 2 * DIM]);
    }
    __half2* xd = (__half2*)x16;
    __half2* wd = (__half2*)wpk;
    for (int j = i; j < NX2 + 4 * NW2; j += stride) {
        float2 v;
        if (j < NX2) {
            v = ((const float2*)x)[j];
            xd[j] = __floats2half2_rn(v.x, v.y);
        } else {
            int k = j - NX2;
            int seg = k / NW2, off = k - seg * NW2;
            const float* W = (seg == 0) ? Wq : (seg == 1) ? Wk : (seg == 2) ? Wv : Wo;
            v = ((const float2*)W)[off];
            wd[k] = __floats2half2_rn(v.x, v.y);
        }
    }
}

// ============================================================
// QKV fused: Y[plane][4096,768] = X @ Wpk[n,:]^T + bqkv.
// N = 2304 over packed weights. BM=128 BN=64 BK=64, 256 thr.
// ============================================================
__global__ __launch_bounds__(256) void qkv16(
    const __half* __restrict__ X, const __half* __restrict__ W,
    const float* __restrict__ bias, __half* __restrict__ QKV)
{
    __shared__ __align__(16) unsigned char smbuf[49152];
    const uint32_t smb = (uint32_t)__cvta_generic_to_shared(smbuf);
    const int tid = threadIdx.x, lane = tid & 31, warp = tid >> 5;
    const int wm = warp >> 1, wn = warp & 1;
    const int m0 = blockIdx.y * 128, n0 = blockIdx.x * 64;
    const int g = lane >> 2, t4 = lane & 3;
    const int plane = n0 / DIM, ncol = n0 - plane * DIM;
    __half* Y = QKV + (size_t)plane * SEQ * DIM;

    float c[2][4][4];
#pragma unroll
    for (int mt = 0; mt < 2; mt++)
#pragma unroll
        for (int nt = 0; nt < 4; nt++)
#pragma unroll
            for (int r = 0; r < 4; r++) c[mt][nt][r] = 0.f;

    {
        uint32_t ab = smb, bb = smb + 16384;
#pragma unroll
        for (int i = 0; i < 4; i++) {
            int op = tid + i * 256; int row = op >> 3, ch = op & 7;
            cp16(ab + swz(row, ch), X + (size_t)(m0 + row) * DIM + ch * 8);
        }
#pragma unroll
        for (int i = 0; i < 2; i++) {
            int op = tid + i * 256; int row = op >> 3, ch = op & 7;
            cp16(bb + swz(row, ch), W + (size_t)(n0 + row) * DIM + ch * 8);
        }
        CP_COMMIT();
    }

    for (int it = 0; it < 12; it++) {
        if (it < 11) {
            int kt = (it + 1) * 64;
            uint32_t ab = smb + ((it + 1) & 1) * 24576, bb = ab + 16384;
#pragma unroll
            for (int i = 0; i < 4; i++) {
                int op = tid + i * 256; int row = op >> 3, ch = op & 7;
                cp16(ab + swz(row, ch), X + (size_t)(m0 + row) * DIM + kt + ch * 8);
            }
#pragma unroll
            for (int i = 0; i < 2; i++) {
                int op = tid + i * 256; int row = op >> 3, ch = op & 7;
                cp16(bb + swz(row, ch), W + (size_t)(n0 + row) * DIM + kt + ch * 8);
            }
            CP_COMMIT();
            CP_WAIT1();
        } else {
            CP_WAIT0();
        }
        __syncthreads();

        uint32_t ab = smb + (it & 1) * 24576, bb = ab + 16384;
#pragma unroll
        for (int ks = 0; ks < 4; ks++) {
            uint32_t a[2][4], b[2][4];
#pragma unroll
            for (int mt = 0; mt < 2; mt++) {
                int row = wm * 32 + mt * 16 + (lane & 15);
                int ch = ks * 2 + (lane >> 4);
                LDSM4(a[mt], ab + swz(row, ch));
            }
#pragma unroll
            for (int p = 0; p < 2; p++) {
                int row = wn * 32 + p * 16 + (lane & 7) + ((lane >> 4) << 3);
                int ch = ks * 2 + ((lane >> 3) & 1);
                LDSM4(b[p], bb + swz(row, ch));
            }
#pragma unroll
            for (int mt = 0; mt < 2; mt++) {
                mma16(c[mt][0], a[mt], &b[0][0]);
                mma16(c[mt][1], a[mt], &b[0][2]);
                mma16(c[mt][2], a[mt], &b[1][0]);
                mma16(c[mt][3], a[mt], &b[1][2]);
            }
        }
        __syncthreads();
    }

#pragma unroll
    for (int mt = 0; mt < 2; mt++)
#pragma unroll
        for (int nt = 0; nt < 4; nt++) {
            int cg = n0 + wn * 32 + nt * 8 + t4 * 2;
            float b0 = bias[cg], b1 = bias[cg + 1];
            int col = ncol + wn * 32 + nt * 8 + t4 * 2;
#pragma unroll
            for (int rh = 0; rh < 2; rh++) {
                int row = m0 + wm * 32 + mt * 16 + g + rh * 8;
                *(__half2*)(Y + (size_t)row * DIM + col) =
                    __floats2half2_rn(c[mt][nt][rh * 2] + b0, c[mt][nt][rh * 2 + 1] + b1);
            }
        }
}

// ============================================================
// Final linear: out[4096,768] fp32 = A @ Wo^T + bo.
// ============================================================
__global__ __launch_bounds__(256) void oproj16(
    const __half* __restrict__ X, const __half* __restrict__ W,
    const float* __restrict__ bias, float* __restrict__ Y)
{
    __shared__ __align__(16) unsigned char smbuf[49152];
    const uint32_t smb = (uint32_t)__cvta_generic_to_shared(smbuf);
    const int tid = threadIdx.x, lane = tid & 31, warp = tid >> 5;
    const int wm = warp >> 1, wn = warp & 1;
    const int m0 = blockIdx.y * 128, n0 = blockIdx.x * 64;
    const int g = lane >> 2, t4 = lane & 3;

    float c[2][4][4];
#pragma unroll
    for (int mt = 0; mt < 2; mt++)
#pragma unroll
        for (int nt = 0; nt < 4; nt++)
#pragma unroll
            for (int r = 0; r < 4; r++) c[mt][nt][r] = 0.f;

    {
        uint32_t ab = smb, bb = smb + 16384;
#pragma unroll
        for (int i = 0; i < 4; i++) {
            int op = tid + i * 256; int row = op >> 3, ch = op & 7;
            cp16(ab + swz(row, ch), X + (size_t)(m0 + row) * DIM + ch * 8);
        }
#pragma unroll
        for (int i = 0; i < 2; i++) {
            int op = tid + i * 256; int row = op >> 3, ch = op & 7;
            cp16(bb + swz(row, ch), W + (size_t)(n0 + row) * DIM + ch * 8);
        }
        CP_COMMIT();
    }

    for (int it = 0; it < 12; it++) {
        if (it < 11) {
            int kt = (it + 1) * 64;
            uint32_t ab = smb + ((it + 1) & 1) * 24576, bb = ab + 16384;
#pragma unroll
            for (int i = 0; i < 4; i++) {
                int op = tid + i * 256; int row = op >> 3, ch = op & 7;
                cp16(ab + swz(row, ch), X + (size_t)(m0 + row) * DIM + kt + ch * 8);
            }
#pragma unroll
            for (int i = 0; i < 2; i++) {
                int op = tid + i * 256; int row = op >> 3, ch = op & 7;
                cp16(bb + swz(row, ch), W + (size_t)(n0 + row) * DIM + kt + ch * 8);
            }
            CP_COMMIT();
            CP_WAIT1();
        } else {
            CP_WAIT0();
        }
        __syncthreads();

        uint32_t ab = smb + (it & 1) * 24576, bb = ab + 16384;
#pragma unroll
        for (int ks = 0; ks < 4; ks++) {
            uint32_t a[2][4], b[2][4];
#pragma unroll
            for (int mt = 0; mt < 2; mt++) {
                int row = wm * 32 + mt * 16 + (lane & 15);
                int ch = ks * 2 + (lane >> 4);
                LDSM4(a[mt], ab + swz(row, ch));
            }
#pragma unroll
            for (int p = 0; p < 2; p++) {
                int row = wn * 32 + p * 16 + (lane & 7) + ((lane >> 4) << 3);
                int ch = ks * 2 + ((lane >> 3) & 1);
                LDSM4(b[p], bb + swz(row, ch));
            }
#pragma unroll
            for (int mt = 0; mt < 2; mt++) {
                mma16(c[mt][0], a[mt], &b[0][0]);
                mma16(c[mt][1], a[mt], &b[0][2]);
                mma16(c[mt][2], a[mt], &b[1][0]);
                mma16(c[mt][3], a[mt], &b[1][2]);
            }
        }
        __syncthreads();
    }

#pragma unroll
    for (int mt = 0; mt < 2; mt++)
#pragma unroll
        for (int nt = 0; nt < 4; nt++) {
            int col = n0 + wn * 32 + nt * 8 + t4 * 2;
            float b0 = bias[col], b1 = bias[col + 1];
#pragma unroll
            for (int rh = 0; rh < 2; rh++) {
                int row = m0 + wm * 32 + mt * 16 + g + rh * 8;
                float2 v = {c[mt][nt][rh * 2] + b0, c[mt][nt][rh * 2 + 1] + b1};
                *(float2*)(Y + (size_t)row * DIM + col) = v;
            }
        }
}

// ============================================================
// Scores + head-softmax. CTA tile 64(s) x 64(t), 512 threads,
// 16 warps (4s x 4t), warp tile m16 x n16. Scores staged in
// smem fp32 (12 x 64 x 64, row-xor swizzle), softmax over h,
// coalesced half2 P stores.
// ============================================================
#define SC_BYTES  (12 * 64 * 64 * 4)   // 196608
#define STG_OFF   SC_BYTES
#define SC_SMEM   (SC_BYTES + 2 * 16384)  // 229376

__global__ __launch_bounds__(512) void scores16(
    const __half* __restrict__ Qh, const __half* __restrict__ Kh,
    __half* __restrict__ P)
{
    extern __shared__ __align__(16) unsigned char sm[];
    float* sc = (float*)sm;
    const uint32_t smb = (uint32_t)__cvta_generic_to_shared(sm);
    const uint32_t stg = smb + STG_OFF;
    const int tid = threadIdx.x, lane = tid & 31, warp = tid >> 5;
    const int wm = warp >> 2, wn = warp & 3;
    const int s0 = blockIdx.y * 64, t0 = blockIdx.x * 64;
    const int g = lane >> 2, t4 = lane & 3;
    const int row8 = tid >> 3, ch8 = tid & 7;

    // prologue: head 0 K (8KB) + Q (8KB) into buf 0
    cp16(stg + swz(row8, ch8), Kh + (size_t)(s0 + row8) * DIM + ch8 * 8);
    cp16(stg + 8192 + swz(row8, ch8), Qh + (size_t)(t0 + row8) * DIM + ch8 * 8);
    CP_COMMIT();

#pragma unroll
    for (int h = 0; h < NHEAD; h++) {
        if (h < NHEAD - 1) {
            uint32_t base = stg + ((h + 1) & 1) * 16384;
            int hc = (h + 1) * DHEAD;
            cp16(base + swz(row8, ch8), Kh + (size_t)(s0 + row8) * DIM + hc + ch8 * 8);
            cp16(base + 8192 + swz(row8, ch8), Qh + (size_t)(t0 + row8) * DIM + hc + ch8 * 8);
            CP_COMMIT();
            CP_WAIT1();
        } else {
            CP_WAIT0();
        }
        __syncthreads();

        uint32_t kb = stg + (h & 1) * 16384, qb = kb + 8192;
        float acc[2][4];
#pragma unroll
        for (int nt = 0; nt < 2; nt++)
#pragma unroll
            for (int r = 0; r < 4; r++) acc[nt][r] = 0.f;

#pragma unroll
        for (int ks = 0; ks < 4; ks++) {
            uint32_t a[4], b[4];
            {
                int row = wm * 16 + (lane & 15);
                int ch = ks * 2 + (lane >> 4);
                LDSM4(a, kb + swz(row, ch));
            }
            {
                int row = wn * 16 + (lane & 7) + ((lane >> 4) << 3);
                int ch = ks * 2 + ((lane >> 3) & 1);
                LDSM4(b, qb + swz(row, ch));
            }
            mma16(acc[0], a, &b[0]);
            mma16(acc[1], a, &b[2]);
        }

        // store scores (float2, row-xor swizzle keeps pairs adjacent)
#pragma unroll
        for (int nt = 0; nt < 2; nt++)
#pragma unroll
            for (int rh = 0; rh < 2; rh++) {
                int r = wm * 16 + g + rh * 8;
                int col = wn * 16 + nt * 8 + t4 * 2;
                float2 v = {acc[nt][rh * 2], acc[nt][rh * 2 + 1]};
                *(float2*)&sc[h * 4096 + r * 64 + (col ^ ((r & 7) << 3))] = v;
            }
        __syncthreads();
    }

    // softmax over heads per (s, t-pair); coalesced half2 P stores
#pragma unroll
    for (int i = 0; i < 4; i++) {
        int p = tid + i * 512;           // 2048 pairs
        int s = p >> 5, tp = p & 31;
        int base = s * 64 + ((2 * tp) ^ ((s & 7) << 3));
        float ex[NHEAD], ey[NHEAD];
        float zx = 0.f, zy = 0.f;
#pragma unroll
        for (int h = 0; h < NHEAD; h++) {
            float2 v = *(const float2*)&sc[h * 4096 + base];
            ex[h] = __expf(v.x); ey[h] = __expf(v.y);
            zx += ex[h]; zy += ey[h];
        }
        float ix = POST_SCALE / zx, iy = POST_SCALE / zy;
#pragma unroll
        for (int h = 0; h < NHEAD; h++) {
            *(__half2*)(P + ((size_t)h * SEQ + s0 + s) * SEQ + t0 + 2 * tp) =
                __floats2half2_rn(ex[h] * ix, ey[h] * iy);
        }
    }
}

// ============================================================
// PV: out[s, h*64+d] = sum_t P[h,s,t] * V[t, h*64+d], fp16 out.
// BM=64, BN=64, BK=64. 256 threads, 8 warps (4m x 2n).
// ============================================================
__global__ __launch_bounds__(256) void pv16(
    const __half* __restrict__ P, const __half* __restrict__ V,
    __half* __restrict__ Y)
{
    __shared__ __align__(16) unsigned char smbuf[32768];
    const uint32_t smb = (uint32_t)__cvta_generic_to_shared(smbuf);
    const int tid = threadIdx.x, lane = tid & 31, warp = tid >> 5;
    const int wm = warp >> 1, wn = warp & 1;
    const int h = blockIdx.z;
    const int m0 = blockIdx.y * 64;
    const int g = lane >> 2, t4 = lane & 3;
    const __half* Ph = P + (size_t)h * SEQ * SEQ;

    float c[4][4];
#pragma unroll
    for (int nt = 0; nt < 4; nt++)
#pragma unroll
        for (int r = 0; r < 4; r++) c[nt][r] = 0.f;

    {
        uint32_t ab = smb, bb = smb + 8192;
#pragma unroll
        for (int i = 0; i < 2; i++) {
            int op = tid + i * 256; int row = op >> 3, ch = op & 7;
            cp16(ab + swz(row, ch), Ph + (size_t)(m0 + row) * SEQ + ch * 8);
        }
#pragma unroll
        for (int i = 0; i < 2; i++) {
            int op = tid + i * 256; int row = op >> 3, ch = op & 7;
            cp16(bb + swz(row, ch), V + (size_t)row * DIM + h * DHEAD + ch * 8);
        }
        CP_COMMIT();
    }

    for (int it = 0; it < 64; it++) {
        if (it < 63) {
            int kt = (it + 1) * 64;
            uint32_t ab = smb + ((it + 1) & 1) * 16384, bb = ab + 8192;
#pragma unroll
            for (int i = 0; i < 2; i++) {
                int op = tid + i * 256; int row = op >> 3, ch = op & 7;
                cp16(ab + swz(row, ch), Ph + (size_t)(m0 + row) * SEQ + kt + ch * 8);
            }
#pragma unroll
            for (int i = 0; i < 2; i++) {
                int op = tid + i * 256; int row = op >> 3, ch = op & 7;
                cp16(bb + swz(row, ch), V + (size_t)(kt + row) * DIM + h * DHEAD + ch * 8);
            }
            CP_COMMIT();
            CP_WAIT1();
        } else {
            CP_WAIT0();
        }
        __syncthreads();

        uint32_t ab = smb + (it & 1) * 16384, bb = ab + 8192;
#pragma unroll
        for (int ks = 0; ks < 4; ks++) {
            uint32_t a[4], b[2][4];
            {
                int row = wm * 16 + (lane & 15);
                int ch = ks * 2 + (lane >> 4);
                LDSM4(a, ab + swz(row, ch));
            }
#pragma unroll
            for (int p = 0; p < 2; p++) {
                int row = ks * 16 + (lane & 15);
                int ch = wn * 4 + p * 2 + (lane >> 4);
                LDSM4T(b[p], bb + swz(row, ch));
            }
            mma16(c[0], a, &b[0][0]);
            mma16(c[1], a, &b[0][2]);
            mma16(c[2], a, &b[1][0]);
            mma16(c[3], a, &b[1][2]);
        }
        __syncthreads();
    }

#pragma unroll
    for (int nt = 0; nt < 4; nt++) {
        int col = h * DHEAD + wn * 32 + nt * 8 + t4 * 2;
#pragma unroll
        for (int rh = 0; rh < 2; rh++) {
            int row = m0 + wm * 16 + g + rh * 8;
            *(__half2*)(Y + (size_t)row * DIM + col) =
                __floats2half2_rn(c[nt][rh * 2], c[nt][rh * 2 + 1]);
        }
    }
}

// ============================================================
extern "C" void kernel_launch(void* const* d_in, const int* in_sizes, int n_in,
                              void* d_out, int out_size)
{
    const float* x  = (const float*)d_in[0];
    const float* Wq = (const float*)d_in[1];
    const float* bq = (const float*)d_in[2];
    const float* Wk = (const float*)d_in[3];
    const float* bk = (const float*)d_in[4];
    const float* Wv = (const float*)d_in[5];
    const float* bv = (const float*)d_in[6];
    const float* Wo = (const float*)d_in[7];
    const float* bo = (const float*)d_in[8];
    float* out = (float*)d_out;

    __half *x16, *wpk, *QKV, *Ah, *P;
    float* bqkv;
    cudaGetSymbolAddress((void**)&x16, g_x16);
    cudaGetSymbolAddress((void**)&wpk, g_w);
    cudaGetSymbolAddress((void**)&bqkv, g_bqkv);
    cudaGetSymbolAddress((void**)&QKV, g_QKV);
    cudaGetSymbolAddress((void**)&Ah, g_Ah);
    cudaGetSymbolAddress((void**)&P, g_P);

    cudaFuncSetAttribute(scores16, cudaFuncAttributeMaxDynamicSharedMemorySize, SC_SMEM);

    cvt_all<<<2048, 256>>>(x, Wq, Wk, Wv, Wo, bq, bk, bv, x16, wpk, bqkv);

    dim3 gqkv(3 * DIM / 64, SEQ / 128);
    qkv16<<<gqkv, 256>>>(x16, wpk, bqkv, QKV);

    const __half* Qh = QKV;
    const __half* Kh = QKV + (size_t)SEQ * DIM;
    const __half* Vh = QKV + (size_t)2 * SEQ * DIM;

    dim3 gsc(SEQ / 64, SEQ / 64);
    scores16<<<gsc, 512, SC_SMEM>>>(Qh, Kh, P);

    dim3 gpv(1, SEQ / 64, NHEAD);
    pv16<<<gpv, 256>>>(P, Vh, Ah);

    dim3 glin(DIM / 64, SEQ / 128);
    oproj16<<<glin, 256>>>(Ah, wpk + (size_t)3 * DIM * DIM, bo, out);
}

// round 4
// speedup vs baseline: 4.1856x; 1.0010x over previous
#include <cuda_runtime.h>
#include <cuda_fp16.h>
#include <cstdint>

#define SEQ 4096
#define DIM 768
#define NHEAD 12
#define DHEAD 64
#define POST_SCALE 19.595917942265423f  // sqrt(384)

// ---- device scratch (allocation-free rule) ----
__device__ __half g_x16[SEQ * DIM];
__device__ __half g_w[4 * DIM * DIM];          // packed Wq,Wk,Wv,Wo (fp16)
__device__ float  g_bqkv[3 * DIM];             // packed bq,bk,bv
__device__ __half g_QKV[3 * SEQ * DIM];        // Q,K,V planes (fp16)
__device__ __half g_Ah[SEQ * DIM];
__device__ __half g_P[(size_t)NHEAD * SEQ * SEQ];  // 402 MB

// ---------------- PTX helpers ----------------
__device__ __forceinline__ void cp16(uint32_t dst, const void* src) {
    asm volatile("cp.async.cg.shared.global [%0], [%1], 16;\n" :: "r"(dst), "l"(src));
}
#define CP_COMMIT() asm volatile("cp.async.commit_group;\n")
#define CP_WAIT0()  asm volatile("cp.async.wait_group 0;\n")
#define CP_WAIT1()  asm volatile("cp.async.wait_group 1;\n")

#define LDSM4(R, a) asm volatile( \
    "ldmatrix.sync.aligned.m8n8.x4.shared.b16 {%0,%1,%2,%3}, [%4];" \
    : "=r"((R)[0]), "=r"((R)[1]), "=r"((R)[2]), "=r"((R)[3]) : "r"(a))
#define LDSM4T(R, a) asm volatile( \
    "ldmatrix.sync.aligned.m8n8.x4.trans.shared.b16 {%0,%1,%2,%3}, [%4];" \
    : "=r"((R)[0]), "=r"((R)[1]), "=r"((R)[2]), "=r"((R)[3]) : "r"(a))

__device__ __forceinline__ void mma16(float* c, const uint32_t* a, const uint32_t* b) {
    asm volatile(
        "mma.sync.aligned.m16n8k16.row.col.f32.f16.f16.f32 "
        "{%0,%1,%2,%3},{%4,%5,%6,%7},{%8,%9},{%0,%1,%2,%3};\n"
        : "+f"(c[0]), "+f"(c[1]), "+f"(c[2]), "+f"(c[3])
        : "r"(a[0]), "r"(a[1]), "r"(a[2]), "r"(a[3]), "r"(b[0]), "r"(b[1]));
}

// swizzled byte offset within a tile of 128B rows (8x16B chunks, chunk ^= row&7)
__device__ __forceinline__ uint32_t swz(int row, int ch) {
    return (uint32_t)(row * 128 + ((ch ^ (row & 7)) << 4));
}

// ---------------- merged fp32->fp16 convert + packing ----------------
#define NX2 (SEQ * DIM / 2)
#define NW2 (DIM * DIM / 2)
__global__ void cvt_all(
    const float* __restrict__ x,
    const float* __restrict__ Wq, const float* __restrict__ Wk,
    const float* __restrict__ Wv, const float* __restrict__ Wo,
    const float* __restrict__ bq, const float* __restrict__ bk,
    const float* __restrict__ bv,
    __half* __restrict__ x16, __half* __restrict__ wpk,
    float* __restrict__ bqkv)
{
    int i = blockIdx.x * blockDim.x + threadIdx.x;
    int stride = gridDim.x * blockDim.x;
    if (i < 3 * DIM) {
        bqkv[i] = (i < DIM) ? bq[i] : (i < 2 * DIM ? bk[i - DIM] : bv[i - 2 * DIM]);
    }
    __half2* xd = (__half2*)x16;
    __half2* wd = (__half2*)wpk;
    for (int j = i; j < NX2 + 4 * NW2; j += stride) {
        float2 v;
        if (j < NX2) {
            v = ((const float2*)x)[j];
            xd[j] = __floats2half2_rn(v.x, v.y);
        } else {
            int k = j - NX2;
            int seg = k / NW2, off = k - seg * NW2;
            const float* W = (seg == 0) ? Wq : (seg == 1) ? Wk : (seg == 2) ? Wv : Wo;
            v = ((const float2*)W)[off];
            wd[k] = __floats2half2_rn(v.x, v.y);
        }
    }
}

// ============================================================
// QKV fused: Y[plane][4096,768] = X @ Wpk[n,:]^T + bqkv.
// N = 2304 over packed weights. BM=128 BN=64 BK=64, 256 thr.
// ============================================================
__global__ __launch_bounds__(256) void qkv16(
    const __half* __restrict__ X, const __half* __restrict__ W,
    const float* __restrict__ bias, __half* __restrict__ QKV)
{
    __shared__ __align__(16) unsigned char smbuf[49152];
    const uint32_t smb = (uint32_t)__cvta_generic_to_shared(smbuf);
    const int tid = threadIdx.x, lane = tid & 31, warp = tid >> 5;
    const int wm = warp >> 1, wn = warp & 1;
    const int m0 = blockIdx.y * 128, n0 = blockIdx.x * 64;
    const int g = lane >> 2, t4 = lane & 3;
    const int plane = n0 / DIM, ncol = n0 - plane * DIM;
    __half* Y = QKV + (size_t)plane * SEQ * DIM;

    float c[2][4][4];
#pragma unroll
    for (int mt = 0; mt < 2; mt++)
#pragma unroll
        for (int nt = 0; nt < 4; nt++)
#pragma unroll
            for (int r = 0; r < 4; r++) c[mt][nt][r] = 0.f;

    {
        uint32_t ab = smb, bb = smb + 16384;
#pragma unroll
        for (int i = 0; i < 4; i++) {
            int op = tid + i * 256; int row = op >> 3, ch = op & 7;
            cp16(ab + swz(row, ch), X + (size_t)(m0 + row) * DIM + ch * 8);
        }
#pragma unroll
        for (int i = 0; i < 2; i++) {
            int op = tid + i * 256; int row = op >> 3, ch = op & 7;
            cp16(bb + swz(row, ch), W + (size_t)(n0 + row) * DIM + ch * 8);
        }
        CP_COMMIT();
    }

    for (int it = 0; it < 12; it++) {
        if (it < 11) {
            int kt = (it + 1) * 64;
            uint32_t ab = smb + ((it + 1) & 1) * 24576, bb = ab + 16384;
#pragma unroll
            for (int i = 0; i < 4; i++) {
                int op = tid + i * 256; int row = op >> 3, ch = op & 7;
                cp16(ab + swz(row, ch), X + (size_t)(m0 + row) * DIM + kt + ch * 8);
            }
#pragma unroll
            for (int i = 0; i < 2; i++) {
                int op = tid + i * 256; int row = op >> 3, ch = op & 7;
                cp16(bb + swz(row, ch), W + (size_t)(n0 + row) * DIM + kt + ch * 8);
            }
            CP_COMMIT();
            CP_WAIT1();
        } else {
            CP_WAIT0();
        }
        __syncthreads();

        uint32_t ab = smb + (it & 1) * 24576, bb = ab + 16384;
#pragma unroll
        for (int ks = 0; ks < 4; ks++) {
            uint32_t a[2][4], b[2][4];
#pragma unroll
            for (int mt = 0; mt < 2; mt++) {
                int row = wm * 32 + mt * 16 + (lane & 15);
                int ch = ks * 2 + (lane >> 4);
                LDSM4(a[mt], ab + swz(row, ch));
            }
#pragma unroll
            for (int p = 0; p < 2; p++) {
                int row = wn * 32 + p * 16 + (lane & 7) + ((lane >> 4) << 3);
                int ch = ks * 2 + ((lane >> 3) & 1);
                LDSM4(b[p], bb + swz(row, ch));
            }
#pragma unroll
            for (int mt = 0; mt < 2; mt++) {
                mma16(c[mt][0], a[mt], &b[0][0]);
                mma16(c[mt][1], a[mt], &b[0][2]);
                mma16(c[mt][2], a[mt], &b[1][0]);
                mma16(c[mt][3], a[mt], &b[1][2]);
            }
        }
        __syncthreads();
    }

#pragma unroll
    for (int mt = 0; mt < 2; mt++)
#pragma unroll
        for (int nt = 0; nt < 4; nt++) {
            int cg = n0 + wn * 32 + nt * 8 + t4 * 2;
            float b0 = bias[cg], b1 = bias[cg + 1];
            int col = ncol + wn * 32 + nt * 8 + t4 * 2;
#pragma unroll
            for (int rh = 0; rh < 2; rh++) {
                int row = m0 + wm * 32 + mt * 16 + g + rh * 8;
                *(__half2*)(Y + (size_t)row * DIM + col) =
                    __floats2half2_rn(c[mt][nt][rh * 2] + b0, c[mt][nt][rh * 2 + 1] + b1);
            }
        }
}

// ============================================================
// Final linear: out[4096,768] fp32 = A @ Wo^T + bo.
// ============================================================
__global__ __launch_bounds__(256) void oproj16(
    const __half* __restrict__ X, const __half* __restrict__ W,
    const float* __restrict__ bias, float* __restrict__ Y)
{
    __shared__ __align__(16) unsigned char smbuf[49152];
    const uint32_t smb = (uint32_t)__cvta_generic_to_shared(smbuf);
    const int tid = threadIdx.x, lane = tid & 31, warp = tid >> 5;
    const int wm = warp >> 1, wn = warp & 1;
    const int m0 = blockIdx.y * 128, n0 = blockIdx.x * 64;
    const int g = lane >> 2, t4 = lane & 3;

    float c[2][4][4];
#pragma unroll
    for (int mt = 0; mt < 2; mt++)
#pragma unroll
        for (int nt = 0; nt < 4; nt++)
#pragma unroll
            for (int r = 0; r < 4; r++) c[mt][nt][r] = 0.f;

    {
        uint32_t ab = smb, bb = smb + 16384;
#pragma unroll
        for (int i = 0; i < 4; i++) {
            int op = tid + i * 256; int row = op >> 3, ch = op & 7;
            cp16(ab + swz(row, ch), X + (size_t)(m0 + row) * DIM + ch * 8);
        }
#pragma unroll
        for (int i = 0; i < 2; i++) {
            int op = tid + i * 256; int row = op >> 3, ch = op & 7;
            cp16(bb + swz(row, ch), W + (size_t)(n0 + row) * DIM + ch * 8);
        }
        CP_COMMIT();
    }

    for (int it = 0; it < 12; it++) {
        if (it < 11) {
            int kt = (it + 1) * 64;
            uint32_t ab = smb + ((it + 1) & 1) * 24576, bb = ab + 16384;
#pragma unroll
            for (int i = 0; i < 4; i++) {
                int op = tid + i * 256; int row = op >> 3, ch = op & 7;
                cp16(ab + swz(row, ch), X + (size_t)(m0 + row) * DIM + kt + ch * 8);
            }
#pragma unroll
            for (int i = 0; i < 2; i++) {
                int op = tid + i * 256; int row = op >> 3, ch = op & 7;
                cp16(bb + swz(row, ch), W + (size_t)(n0 + row) * DIM + kt + ch * 8);
            }
            CP_COMMIT();
            CP_WAIT1();
        } else {
            CP_WAIT0();
        }
        __syncthreads();

        uint32_t ab = smb + (it & 1) * 24576, bb = ab + 16384;
#pragma unroll
        for (int ks = 0; ks < 4; ks++) {
            uint32_t a[2][4], b[2][4];
#pragma unroll
            for (int mt = 0; mt < 2; mt++) {
                int row = wm * 32 + mt * 16 + (lane & 15);
                int ch = ks * 2 + (lane >> 4);
                LDSM4(a[mt], ab + swz(row, ch));
            }
#pragma unroll
            for (int p = 0; p < 2; p++) {
                int row = wn * 32 + p * 16 + (lane & 7) + ((lane >> 4) << 3);
                int ch = ks * 2 + ((lane >> 3) & 1);
                LDSM4(b[p], bb + swz(row, ch));
            }
#pragma unroll
            for (int mt = 0; mt < 2; mt++) {
                mma16(c[mt][0], a[mt], &b[0][0]);
                mma16(c[mt][1], a[mt], &b[0][2]);
                mma16(c[mt][2], a[mt], &b[1][0]);
                mma16(c[mt][3], a[mt], &b[1][2]);
            }
        }
        __syncthreads();
    }

#pragma unroll
    for (int mt = 0; mt < 2; mt++)
#pragma unroll
        for (int nt = 0; nt < 4; nt++) {
            int col = n0 + wn * 32 + nt * 8 + t4 * 2;
            float b0 = bias[col], b1 = bias[col + 1];
#pragma unroll
            for (int rh = 0; rh < 2; rh++) {
                int row = m0 + wm * 32 + mt * 16 + g + rh * 8;
                float2 v = {c[mt][nt][rh * 2] + b0, c[mt][nt][rh * 2 + 1] + b1};
                *(float2*)(Y + (size_t)row * DIM + col) = v;
            }
        }
}

// ============================================================
// Scores + head-softmax. CTA tile 64(s) x 64(t), 512 threads,
// 16 warps (4s x 4t), warp tile m16 x n16. Scores staged in
// smem fp32 (12 x 64 x 64, row-xor swizzle), softmax over h,
// coalesced half2 P stores.
// ============================================================
#define SC_BYTES  (12 * 64 * 64 * 4)   // 196608
#define STG_OFF   SC_BYTES
#define SC_SMEM   (SC_BYTES + 2 * 16384)  // 229376

__global__ __launch_bounds__(512) void scores16(
    const __half* __restrict__ Qh, const __half* __restrict__ Kh,
    __half* __restrict__ P)
{
    extern __shared__ __align__(16) unsigned char sm[];
    float* sc = (float*)sm;
    const uint32_t smb = (uint32_t)__cvta_generic_to_shared(sm);
    const uint32_t stg = smb + STG_OFF;
    const int tid = threadIdx.x, lane = tid & 31, warp = tid >> 5;
    const int wm = warp >> 2, wn = warp & 3;
    const int s0 = blockIdx.y * 64, t0 = blockIdx.x * 64;
    const int g = lane >> 2, t4 = lane & 3;
    const int row8 = tid >> 3, ch8 = tid & 7;

    // prologue: head 0 K (8KB) + Q (8KB) into buf 0
    cp16(stg + swz(row8, ch8), Kh + (size_t)(s0 + row8) * DIM + ch8 * 8);
    cp16(stg + 8192 + swz(row8, ch8), Qh + (size_t)(t0 + row8) * DIM + ch8 * 8);
    CP_COMMIT();

#pragma unroll
    for (int h = 0; h < NHEAD; h++) {
        if (h < NHEAD - 1) {
            uint32_t base = stg + ((h + 1) & 1) * 16384;
            int hc = (h + 1) * DHEAD;
            cp16(base + swz(row8, ch8), Kh + (size_t)(s0 + row8) * DIM + hc + ch8 * 8);
            cp16(base + 8192 + swz(row8, ch8), Qh + (size_t)(t0 + row8) * DIM + hc + ch8 * 8);
            CP_COMMIT();
            CP_WAIT1();
        } else {
            CP_WAIT0();
        }
        __syncthreads();

        uint32_t kb = stg + (h & 1) * 16384, qb = kb + 8192;
        float acc[2][4];
#pragma unroll
        for (int nt = 0; nt < 2; nt++)
#pragma unroll
            for (int r = 0; r < 4; r++) acc[nt][r] = 0.f;

#pragma unroll
        for (int ks = 0; ks < 4; ks++) {
            uint32_t a[4], b[4];
            {
                int row = wm * 16 + (lane & 15);
                int ch = ks * 2 + (lane >> 4);
                LDSM4(a, kb + swz(row, ch));
            }
            {
                int row = wn * 16 + (lane & 7) + ((lane >> 4) << 3);
                int ch = ks * 2 + ((lane >> 3) & 1);
                LDSM4(b, qb + swz(row, ch));
            }
            mma16(acc[0], a, &b[0]);
            mma16(acc[1], a, &b[2]);
        }

        // store scores (float2, row-xor swizzle keeps pairs adjacent)
#pragma unroll
        for (int nt = 0; nt < 2; nt++)
#pragma unroll
            for (int rh = 0; rh < 2; rh++) {
                int r = wm * 16 + g + rh * 8;
                int col = wn * 16 + nt * 8 + t4 * 2;
                float2 v = {acc[nt][rh * 2], acc[nt][rh * 2 + 1]};
                *(float2*)&sc[h * 4096 + r * 64 + (col ^ ((r & 7) << 3))] = v;
            }
        __syncthreads();
    }

    // softmax over heads per (s, t-pair); coalesced half2 P stores
#pragma unroll
    for (int i = 0; i < 4; i++) {
        int p = tid + i * 512;           // 2048 pairs
        int s = p >> 5, tp = p & 31;
        int base = s * 64 + ((2 * tp) ^ ((s & 7) << 3));
        float ex[NHEAD], ey[NHEAD];
        float zx = 0.f, zy = 0.f;
#pragma unroll
        for (int h = 0; h < NHEAD; h++) {
            float2 v = *(const float2*)&sc[h * 4096 + base];
            ex[h] = __expf(v.x); ey[h] = __expf(v.y);
            zx += ex[h]; zy += ey[h];
        }
        float ix = POST_SCALE / zx, iy = POST_SCALE / zy;
#pragma unroll
        for (int h = 0; h < NHEAD; h++) {
            *(__half2*)(P + ((size_t)h * SEQ + s0 + s) * SEQ + t0 + 2 * tp) =
                __floats2half2_rn(ex[h] * ix, ey[h] * iy);
        }
    }
}

// ============================================================
// PV: out[s, h*64+d] = sum_t P[h,s,t] * V[t, h*64+d], fp16 out.
// BM=64, BN=64, BK=64. 256 threads, 8 warps (4m x 2n).
// ============================================================
__global__ __launch_bounds__(256) void pv16(
    const __half* __restrict__ P, const __half* __restrict__ V,
    __half* __restrict__ Y)
{
    __shared__ __align__(16) unsigned char smbuf[32768];
    const uint32_t smb = (uint32_t)__cvta_generic_to_shared(smbuf);
    const int tid = threadIdx.x, lane = tid & 31, warp = tid >> 5;
    const int wm = warp >> 1, wn = warp & 1;
    const int h = blockIdx.z;
    const int m0 = blockIdx.y * 64;
    const int g = lane >> 2, t4 = lane & 3;
    const __half* Ph = P + (size_t)h * SEQ * SEQ;

    float c[4][4];
#pragma unroll
    for (int nt = 0; nt < 4; nt++)
#pragma unroll
        for (int r = 0; r < 4; r++) c[nt][r] = 0.f;

    {
        uint32_t ab = smb, bb = smb + 8192;
#pragma unroll
        for (int i = 0; i < 2; i++) {
            int op = tid + i * 256; int row = op >> 3, ch = op & 7;
            cp16(ab + swz(row, ch), Ph + (size_t)(m0 + row) * SEQ + ch * 8);
        }
#pragma unroll
        for (int i = 0; i < 2; i++) {
            int op = tid + i * 256; int row = op >> 3, ch = op & 7;
            cp16(bb + swz(row, ch), V + (size_t)row * DIM + h * DHEAD + ch * 8);
        }
        CP_COMMIT();
    }

    for (int it = 0; it < 64; it++) {
        if (it < 63) {
            int kt = (it + 1) * 64;
            uint32_t ab = smb + ((it + 1) & 1) * 16384, bb = ab + 8192;
#pragma unroll
            for (int i = 0; i < 2; i++) {
                int op = tid + i * 256; int row = op >> 3, ch = op & 7;
                cp16(ab + swz(row, ch), Ph + (size_t)(m0 + row) * SEQ + kt + ch * 8);
            }
#pragma unroll
            for (int i = 0; i < 2; i++) {
                int op = tid + i * 256; int row = op >> 3, ch = op & 7;
                cp16(bb + swz(row, ch), V + (size_t)(kt + row) * DIM + h * DHEAD + ch * 8);
            }
            CP_COMMIT();
            CP_WAIT1();
        } else {
            CP_WAIT0();
        }
        __syncthreads();

        uint32_t ab = smb + (it & 1) * 16384, bb = ab + 8192;
#pragma unroll
        for (int ks = 0; ks < 4; ks++) {
            uint32_t a[4], b[2][4];
            {
                int row = wm * 16 + (lane & 15);
                int ch = ks * 2 + (lane >> 4);
                LDSM4(a, ab + swz(row, ch));
            }
#pragma unroll
            for (int p = 0; p < 2; p++) {
                int row = ks * 16 + (lane & 15);
                int ch = wn * 4 + p * 2 + (lane >> 4);
                LDSM4T(b[p], bb + swz(row, ch));
            }
            mma16(c[0], a, &b[0][0]);
            mma16(c[1], a, &b[0][2]);
            mma16(c[2], a, &b[1][0]);
            mma16(c[3], a, &b[1][2]);
        }
        __syncthreads();
    }

#pragma unroll
    for (int nt = 0; nt < 4; nt++) {
        int col = h * DHEAD + wn * 32 + nt * 8 + t4 * 2;
#pragma unroll
        for (int rh = 0; rh < 2; rh++) {
            int row = m0 + wm * 16 + g + rh * 8;
            *(__half2*)(Y + (size_t)row * DIM + col) =
                __floats2half2_rn(c[nt][rh * 2], c[nt][rh * 2 + 1]);
        }
    }
}

// ============================================================
extern "C" void kernel_launch(void* const* d_in, const int* in_sizes, int n_in,
                              void* d_out, int out_size)
{
    const float* x  = (const float*)d_in[0];
    const float* Wq = (const float*)d_in[1];
    const float* bq = (const float*)d_in[2];
    const float* Wk = (const float*)d_in[3];
    const float* bk = (const float*)d_in[4];
    const float* Wv = (const float*)d_in[5];
    const float* bv = (const float*)d_in[6];
    const float* Wo = (const float*)d_in[7];
    const float* bo = (const float*)d_in[8];
    float* out = (float*)d_out;

    __half *x16, *wpk, *QKV, *Ah, *P;
    float* bqkv;
    cudaGetSymbolAddress((void**)&x16, g_x16);
    cudaGetSymbolAddress((void**)&wpk, g_w);
    cudaGetSymbolAddress((void**)&bqkv, g_bqkv);
    cudaGetSymbolAddress((void**)&QKV, g_QKV);
    cudaGetSymbolAddress((void**)&Ah, g_Ah);
    cudaGetSymbolAddress((void**)&P, g_P);

    cudaFuncSetAttribute(scores16, cudaFuncAttributeMaxDynamicSharedMemorySize, SC_SMEM);

    cvt_all<<<2048, 256>>>(x, Wq, Wk, Wv, Wo, bq, bk, bv, x16, wpk, bqkv);

    dim3 gqkv(3 * DIM / 64, SEQ / 128);
    qkv16<<<gqkv, 256>>>(x16, wpk, bqkv, QKV);

    const __half* Qh = QKV;
    const __half* Kh = QKV + (size_t)SEQ * DIM;
    const __half* Vh = QKV + (size_t)2 * SEQ * DIM;

    dim3 gsc(SEQ / 64, SEQ / 64);
    scores16<<<gsc, 512, SC_SMEM>>>(Qh, Kh, P);

    dim3 gpv(1, SEQ / 64, NHEAD);
    pv16<<<gpv, 256>>>(P, Vh, Ah);

    dim3 glin(DIM / 64, SEQ / 128);
    oproj16<<<glin, 256>>>(Ah, wpk + (size_t)3 * DIM * DIM, bo, out);
}